// round 9
// baseline (speedup 1.0000x reference)
#include <cuda_runtime.h>
#include <cuda_fp16.h>
#include <math.h>
#include <cstdint>

#define BT    4096
#define TSEQ  2048
#define DM    2048
#define DQK   192
#define DV    128
#define NCAT  3712      // 2048(wq) + 1024(wqrot) + 512(wdkv) + 64(wkrot) + 64(pad)
#define ATT_SCALE 0.07216878364870323f   // 1/sqrt(192)
#define NEG_BIG  -1e30f

// ---------------- scratch ----------------
__device__ __half g_x    [BT * DM];
__device__ __half g_wcat [NCAT * DM];       // concatenated projection weights (fp16)
__device__ __half g_wukv_h[4096 * 512];
__device__ __half g_wo_h [DM * DM];
__device__ __half g_qroth[BT * 1024];       // unroped, pre-scaled
__device__ __half g_kroth[BT * 64];         // unroped
__device__ __half g_dkv  [BT * 512];
__device__ __half g_attn [BT * DM];
// packed attention operands
__device__ __half g_qh [32 * TSEQ * DQK];   // [bh][t][192]
__device__ __half g_kh [32 * TSEQ * 128];   // [bh][t][128]
__device__ __half g_krh[ 2 * TSEQ * 64];    // [b][t][64] roped, head-shared
__device__ __half g_vh [32 * TSEQ * 128];   // [bh][t][128]

// ---------------- PTX helpers ----------------
__device__ __forceinline__ void cp16(uint32_t s, const void* g) {
    asm volatile("cp.async.cg.shared.global [%0], [%1], 16;" :: "r"(s), "l"(g) : "memory");
}
__device__ __forceinline__ uint32_t smem_u32(const void* p) {
    uint32_t a;
    asm("{ .reg .u64 t; cvta.to.shared.u64 t, %1; cvt.u32.u64 %0, t; }" : "=r"(a) : "l"(p));
    return a;
}
__device__ __forceinline__ void ldm4(uint32_t* r, uint32_t addr) {
    asm volatile("ldmatrix.sync.aligned.m8n8.x4.shared.b16 {%0,%1,%2,%3}, [%4];"
        : "=r"(r[0]), "=r"(r[1]), "=r"(r[2]), "=r"(r[3]) : "r"(addr));
}
__device__ __forceinline__ void ldm4t(uint32_t* r, uint32_t addr) {
    asm volatile("ldmatrix.sync.aligned.m8n8.x4.trans.shared.b16 {%0,%1,%2,%3}, [%4];"
        : "=r"(r[0]), "=r"(r[1]), "=r"(r[2]), "=r"(r[3]) : "r"(addr));
}
__device__ __forceinline__ void mma16816(float* c, const uint32_t* a, const uint32_t* b) {
    asm volatile(
        "mma.sync.aligned.m16n8k16.row.col.f32.f16.f16.f32 "
        "{%0,%1,%2,%3}, {%4,%5,%6,%7}, {%8,%9}, {%0,%1,%2,%3};"
        : "+f"(c[0]), "+f"(c[1]), "+f"(c[2]), "+f"(c[3])
        : "r"(a[0]), "r"(a[1]), "r"(a[2]), "r"(a[3]), "r"(b[0]), "r"(b[1]));
}
__device__ __forceinline__ void mma16816b(float* c, const uint32_t* a, uint32_t b0, uint32_t b1) {
    asm volatile(
        "mma.sync.aligned.m16n8k16.row.col.f32.f16.f16.f32 "
        "{%0,%1,%2,%3}, {%4,%5,%6,%7}, {%8,%9}, {%0,%1,%2,%3};"
        : "+f"(c[0]), "+f"(c[1]), "+f"(c[2]), "+f"(c[3])
        : "r"(a[0]), "r"(a[1]), "r"(a[2]), "r"(a[3]), "r"(b0), "r"(b1));
}

// ---------------- converts ----------------
__global__ void conv_f16(const float* __restrict__ in, __half* __restrict__ out, int n4) {
    int i = blockIdx.x * blockDim.x + threadIdx.x;
    if (i >= n4) return;
    float4 v = ((const float4*)in)[i];
    ((__half2*)out)[i*2]   = __halves2half2(__float2half_rn(v.x), __float2half_rn(v.y));
    ((__half2*)out)[i*2+1] = __halves2half2(__float2half_rn(v.z), __float2half_rn(v.w));
}
// all four projection weights -> g_wcat (wq, wqrot scaled; wdkv, wkrot unscaled)
__global__ void conv_cat(const float* __restrict__ wq, const float* __restrict__ wqr,
                         const float* __restrict__ wdkv, const float* __restrict__ wkr,
                         __half* __restrict__ out, int n4) {
    int i = blockIdx.x * blockDim.x + threadIdx.x;
    if (i >= n4) return;
    const size_t e = (size_t)i * 4;
    const int row = (int)(e >> 11);
    const float* src;
    size_t local;
    float sc;
    if (row < 2048)      { src = wq;   local = e;                       sc = ATT_SCALE; }
    else if (row < 3072) { src = wqr;  local = e - (size_t)2048 * 2048; sc = ATT_SCALE; }
    else if (row < 3584) { src = wdkv; local = e - (size_t)3072 * 2048; sc = 1.f; }
    else                 { src = wkr;  local = e - (size_t)3584 * 2048; sc = 1.f; }
    float4 v = *(const float4*)(src + local);
    ((__half2*)out)[i*2]   = __halves2half2(__float2half_rn(v.x * sc), __float2half_rn(v.y * sc));
    ((__half2*)out)[i*2+1] = __halves2half2(__float2half_rn(v.z * sc), __float2half_rn(v.w * sc));
}

// ---------------- single-pass fp16 NT GEMM, 3-stage / 1-sync pipeline ----------------
// EPI: 0 fp32 C; 3 ukv split (CH=g_kh, CH2=g_vh, N=4096); 4 fused projection router
template<int BN, int EPI>
__global__ __launch_bounds__(256, 2)
void gemm_s(const __half* __restrict__ A, const __half* __restrict__ B,
            float* __restrict__ C, __half* __restrict__ CH, __half* __restrict__ CH2,
            __half* __restrict__ CH3, __half* __restrict__ CH4,
            int M, int N, int K)
{
    constexpr int ATILE = 128 * 128;
    constexpr int BTILE = BN * 128;
    constexpr int STG   = ATILE + BTILE;
    constexpr int WN = 4;
    constexpr int MT = 4;
    constexpr int NT = 4;

    extern __shared__ __align__(128) char smem[];
    const uint32_t d0 = smem_u32(smem);

    const int tid = threadIdx.x;
    const int wid = tid >> 5, lane = tid & 31;
    const int wn = wid % WN, wm = wid / WN;
    const int m0 = blockIdx.y * 128;
    const int n0 = blockIdx.x * BN;
    const int l7 = lane & 7;

    float acc[MT][NT][4];
#pragma unroll
    for (int i = 0; i < MT; ++i)
#pragma unroll
        for (int j = 0; j < NT; ++j)
#pragma unroll
            for (int q = 0; q < 4; ++q) acc[i][j][q] = 0.f;

    uint32_t arow[MT], brow[NT / 2];
    const int a_r = lane & 15;
    const int a_kh = lane >> 4;
    const int b_n = ((lane >> 4) << 3) + (lane & 7);
    const int b_kh = (lane >> 3) & 1;
#pragma unroll
    for (int mt = 0; mt < MT; ++mt) arow[mt] = (uint32_t)((wm * 64 + mt * 16 + a_r) * 128);
#pragma unroll
    for (int np = 0; np < NT / 2; ++np) brow[np] = (uint32_t)((wn * 32 + np * 16 + b_n) * 128);

    const int T = K >> 6;
    auto load_tile = [&](int t) {
        if (t < T) {
            const uint32_t d = d0 + (uint32_t)(t % 3) * STG;
            const int k0 = t * 64;
#pragma unroll
            for (int j = 0; j < 4; ++j) {
                const int c = tid + j * 256;
                const int row = c >> 3, ch = c & 7;
                const uint32_t sw = (uint32_t)(row * 128 + ((ch ^ (row & 7)) << 4));
                cp16(d + sw, A + (size_t)(m0 + row) * K + k0 + ch * 8);
            }
#pragma unroll
            for (int j = 0; j < BN / 32; ++j) {
                const int c = tid + j * 256;
                const int row = c >> 3, ch = c & 7;
                const uint32_t sw = (uint32_t)(row * 128 + ((ch ^ (row & 7)) << 4));
                cp16(d + ATILE + sw, B + (size_t)(n0 + row) * K + k0 + ch * 8);
            }
        }
        asm volatile("cp.async.commit_group;" ::: "memory");
    };

    load_tile(0);
    load_tile(1);

    for (int t = 0; t < T; ++t) {
        asm volatile("cp.async.wait_group 1;" ::: "memory");
        __syncthreads();
        load_tile(t + 2);

        const uint32_t AS = d0 + (uint32_t)(t % 3) * STG;
        const uint32_t BS = AS + ATILE;

#pragma unroll
        for (int kk = 0; kk < 4; ++kk) {
            const uint32_t aoff = (uint32_t)(((kk * 2 + a_kh) ^ l7) << 4);
            const uint32_t boff = (uint32_t)(((kk * 2 + b_kh) ^ l7) << 4);
            uint32_t af[MT][4], bf[NT / 2][4];
#pragma unroll
            for (int mt = 0; mt < MT; ++mt)
                ldm4(af[mt], AS + arow[mt] + aoff);
#pragma unroll
            for (int np = 0; np < NT / 2; ++np)
                ldm4(bf[np], BS + brow[np] + boff);
#pragma unroll
            for (int mt = 0; mt < MT; ++mt)
#pragma unroll
                for (int nt = 0; nt < NT; ++nt)
                    mma16816(acc[mt][nt], af[mt], &bf[nt >> 1][(nt & 1) * 2]);
        }
    }

    const int cr = lane >> 2;
    const int cc = (lane & 3) * 2;
#pragma unroll
    for (int mt = 0; mt < MT; ++mt) {
        const int r0 = m0 + wm * 64 + mt * 16 + cr;
#pragma unroll
        for (int nt = 0; nt < NT; ++nt) {
            const int col = n0 + wn * 32 + nt * 8 + cc;
            if constexpr (EPI == 0) {
                *(float2*)(C + (size_t)r0 * N + col)       = make_float2(acc[mt][nt][0], acc[mt][nt][1]);
                *(float2*)(C + (size_t)(r0 + 8) * N + col) = make_float2(acc[mt][nt][2], acc[mt][nt][3]);
            } else {
#pragma unroll
                for (int hf = 0; hf < 2; ++hf) {
                    __half2 h2 = __float22half2_rn(
                        make_float2(acc[mt][nt][hf*2], acc[mt][nt][hf*2+1]));
                    const int r = r0 + hf * 8;
                    const int b = r >> 11, tt = r & 2047;
                    if constexpr (EPI == 3) {          // ukv split: K | V
                        const int h = col >> 8, c = col & 255;
                        const size_t base = ((size_t)((b * 16 + h) * 2048 + tt)) * 128;
                        if (c < 128) *(__half2*)(CH  + base + c)         = h2;
                        else         *(__half2*)(CH2 + base + (c - 128)) = h2;
                    } else {                           // EPI == 4: projection router
                        if (col < 2048) {
                            const int h = col >> 7, c = col & 127;
                            *(__half2*)(CH + ((size_t)((b * 16 + h) * 2048 + tt)) * 192 + c) = h2;
                        } else if (col < 3072) {
                            *(__half2*)(CH2 + (size_t)r * 1024 + (col - 2048)) = h2;
                        } else if (col < 3584) {
                            *(__half2*)(CH3 + (size_t)r * 512 + (col - 3072)) = h2;
                        } else if (col < 3648) {
                            *(__half2*)(CH4 + (size_t)r * 64 + (col - 3584)) = h2;
                        }
                    }
                }
            }
        }
    }
}

// ---------------- fused rope + pack (fp16 in / fp16 out) ----------------
__device__ __forceinline__ void rope_pair(float x1, float x2, int i, int t,
                                          float& o1, float& o2) {
    const float invf = (float)exp2(-(double)i * (13.287712379549449 / 32.0));
    const float angf = (float)t * invf;
    double sd, cd;
    sincos((double)angf, &sd, &cd);
    const float s = (float)sd, c = (float)cd;
    o1 = x1 * c - x2 * s;
    o2 = x2 * c + x1 * s;
}
__global__ void rope_pack_q(const __half* __restrict__ qr, __half* __restrict__ oh) {
    int idx = blockIdx.x * blockDim.x + threadIdx.x;   // < 32*2048*32
    int i = idx & 31;
    int rest = idx >> 5;
    int bh = rest >> 11, t = rest & 2047;
    int b = bh >> 4, h = bh & 15;
    const __half* base = qr + ((size_t)(b * TSEQ + t)) * 1024 + h * 64;
    float o1, o2;
    rope_pair(__half2float(base[i]), __half2float(base[i + 32]), i, t, o1, o2);
    __half* dst = oh + ((size_t)bh * TSEQ + t) * DQK + 128;
    dst[i]      = __float2half_rn(o1);
    dst[i + 32] = __float2half_rn(o2);
}
__global__ void rope_pack_k(const __half* __restrict__ kr, __half* __restrict__ oh) {
    int idx = blockIdx.x * blockDim.x + threadIdx.x;   // < 2*2048*32
    int i = idx & 31;
    int rest = idx >> 5;
    int t = rest & 2047;
    const __half* base = kr + (size_t)rest * 64;
    float o1, o2;
    rope_pair(__half2float(base[i]), __half2float(base[i + 32]), i, t, o1, o2);
    __half* dst = oh + (size_t)rest * 64;
    dst[i]      = __float2half_rn(o1);
    dst[i + 32] = __float2half_rn(o2);
}

// ---------------- tensor-core flash attention: BQ=256, 512 threads ----------------
#define QPL  98304           // 256 rows x 384B
#define KPL  24576           // 64 x 384B
#define VPL  16384           // 64 rows x 256B
#define KVSTG (KPL + VPL)    // 40960
#define ATT_SMEM (QPL + 3*KVSTG)   // 221184

__global__ __launch_bounds__(512, 1) void attn_mma(
    const __half* __restrict__ qh, const __half* __restrict__ kh,
    const __half* __restrict__ krh, const __half* __restrict__ vh,
    __half* __restrict__ outh)
{
    extern __shared__ __align__(128) char smem[];
    const uint32_t S0 = smem_u32(smem);
    const int tid = threadIdx.x, wid = tid >> 5, lane = tid & 31;
    const int qt = gridDim.x - 1 - blockIdx.x;      // heavy tiles first
    const int bh = blockIdx.y;
    const int b = bh >> 4, h = bh & 15;
    const int q0 = qt * 256;
    const int nk = 4 * (qt + 1);

    const size_t qbase = (size_t)bh * TSEQ * DQK;
    const size_t kbase = (size_t)bh * TSEQ * 128;
    const size_t rbase = (size_t)b * TSEQ * 64;

    {   // Q (group 0)
        for (int i = tid; i < 256 * 24; i += 512) {
            int row = i / 24, c = i % 24;
            uint32_t sw = (uint32_t)(row * 384 + ((c ^ (row & 7)) << 4));
            cp16(S0 + sw, qh + qbase + (size_t)(q0 + row) * DQK + c * 8);
        }
        asm volatile("cp.async.commit_group;" ::: "memory");
    }
    auto loadKV = [&](int it) {
        if (it < nk) {
            uint32_t d = S0 + QPL + (uint32_t)(it % 3) * KVSTG;
            int k0 = it * 64;
            for (int i = tid; i < 64 * 24; i += 512) {
                int row = i / 24, c = i % 24;
                uint32_t sw = (uint32_t)(row * 384 + ((c ^ (row & 7)) << 4));
                const __half* src = (c < 16)
                    ? kh  + kbase + (size_t)(k0 + row) * 128 + c * 8
                    : krh + rbase + (size_t)(k0 + row) * 64 + (c - 16) * 8;
                cp16(d + sw, src);
            }
            uint32_t dv = d + KPL;
            for (int i = tid; i < 64 * 16; i += 512) {
                int row = i >> 4, c = i & 15;
                uint32_t sw = (uint32_t)(row * 256 + (((c & 8) | ((c & 7) ^ (row & 7))) << 4));
                cp16(dv + sw, vh + kbase + (size_t)(k0 + row) * 128 + c * 8);
            }
        }
        asm volatile("cp.async.commit_group;" ::: "memory");
    };

    loadKV(0);
    loadKV(1);

    const int a_r = lane & 15, a_kh = lane >> 4;
    const int b_n = ((lane >> 4) << 3) + (lane & 7), b_kh = (lane >> 3) & 1;
    const int qrow = wid * 16 + a_r;
    const uint32_t qoff_base = S0 + qrow * 384;
    const int v_tl = lane >> 3, v_r = lane & 7;

    float o[16][4];
#pragma unroll
    for (int j = 0; j < 16; ++j)
#pragma unroll
        for (int q = 0; q < 4; ++q) o[j][q] = 0.f;
    float m0r = NEG_BIG, m1r = NEG_BIG, l0r = 0.f, l1r = 0.f;

    for (int it = 0; it < nk; ++it) {
        asm volatile("cp.async.wait_group 1;" ::: "memory");
        __syncthreads();
        loadKV(it + 2);

        const uint32_t Kb = S0 + QPL + (uint32_t)(it % 3) * KVSTG;
        const uint32_t Vb = Kb + KPL;

        // ---- S = Q K^T ----
        float s[8][4];
#pragma unroll
        for (int j = 0; j < 8; ++j)
#pragma unroll
            for (int q = 0; q < 4; ++q) s[j][q] = 0.f;

#pragma unroll 4
        for (int kc = 0; kc < 12; ++kc) {
            uint32_t qa = qoff_base + ((((kc * 2 + a_kh)) ^ (qrow & 7)) << 4);
            uint32_t qf[4];
            ldm4(qf, qa);
#pragma unroll
            for (int np = 0; np < 4; ++np) {
                int krow = np * 16 + b_n;
                uint32_t ka = Kb + krow * 384 + (((kc * 2 + b_kh) ^ (krow & 7)) << 4);
                uint32_t kf[4];
                ldm4(kf, ka);
#pragma unroll
                for (int t2 = 0; t2 < 2; ++t2)
                    mma16816(s[np * 2 + t2], qf, &kf[t2 * 2]);
            }
        }

        // ---- mask (last four k-tiles only) ----
        const int k0 = it * 64;
        const int r0 = q0 + wid * 16 + (lane >> 2);
        if (it >= nk - 4) {
#pragma unroll
            for (int nt = 0; nt < 8; ++nt) {
                int kcol = k0 + nt * 8 + (lane & 3) * 2;
                if (kcol     > r0)     s[nt][0] = NEG_BIG;
                if (kcol + 1 > r0)     s[nt][1] = NEG_BIG;
                if (kcol     > r0 + 8) s[nt][2] = NEG_BIG;
                if (kcol + 1 > r0 + 8) s[nt][3] = NEG_BIG;
            }
        }

        // ---- online softmax ----
        float mx0 = NEG_BIG, mx1 = NEG_BIG;
#pragma unroll
        for (int nt = 0; nt < 8; ++nt) {
            mx0 = fmaxf(mx0, fmaxf(s[nt][0], s[nt][1]));
            mx1 = fmaxf(mx1, fmaxf(s[nt][2], s[nt][3]));
        }
        mx0 = fmaxf(mx0, __shfl_xor_sync(0xffffffffu, mx0, 1));
        mx0 = fmaxf(mx0, __shfl_xor_sync(0xffffffffu, mx0, 2));
        mx1 = fmaxf(mx1, __shfl_xor_sync(0xffffffffu, mx1, 1));
        mx1 = fmaxf(mx1, __shfl_xor_sync(0xffffffffu, mx1, 2));
        const float mn0 = fmaxf(m0r, mx0), mn1 = fmaxf(m1r, mx1);
        const float al0 = __expf(m0r - mn0), al1 = __expf(m1r - mn1);
        m0r = mn0; m1r = mn1;

        float sum0 = 0.f, sum1 = 0.f;
        uint32_t ph[4][4];
#pragma unroll
        for (int nt = 0; nt < 8; ++nt) {
            float p0 = __expf(s[nt][0] - mn0);
            float p1 = __expf(s[nt][1] - mn0);
            float p2 = __expf(s[nt][2] - mn1);
            float p3 = __expf(s[nt][3] - mn1);
            sum0 += p0 + p1;
            sum1 += p2 + p3;
            __half2 h01 = __float22half2_rn(make_float2(p0, p1));
            __half2 h23 = __float22half2_rn(make_float2(p2, p3));
            const int kc2 = nt >> 1, w2 = (nt & 1) * 2;
            ph[kc2][w2]     = *(uint32_t*)&h01;
            ph[kc2][w2 + 1] = *(uint32_t*)&h23;
        }
        sum0 += __shfl_xor_sync(0xffffffffu, sum0, 1);
        sum0 += __shfl_xor_sync(0xffffffffu, sum0, 2);
        sum1 += __shfl_xor_sync(0xffffffffu, sum1, 1);
        sum1 += __shfl_xor_sync(0xffffffffu, sum1, 2);
        l0r = l0r * al0 + sum0;
        l1r = l1r * al1 + sum1;

#pragma unroll
        for (int j = 0; j < 16; ++j) {
            o[j][0] *= al0; o[j][1] *= al0;
            o[j][2] *= al1; o[j][3] *= al1;
        }

        // ---- O += P V  (V [t][dv] via ldmatrix.trans) ----
#pragma unroll
        for (int kc = 0; kc < 4; ++kc) {
#pragma unroll
            for (int ng = 0; ng < 8; ++ng) {
                const int trow = kc * 16 + ((v_tl >> 1) << 3) + v_r;
                const int c = ng * 2 + (v_tl & 1);
                uint32_t va = Vb + trow * 256 +
                    ((uint32_t)((c & 8) | ((c & 7) ^ (trow & 7))) << 4);
                uint32_t vf[4];
                ldm4t(vf, va);
                mma16816b(o[ng * 2],     ph[kc], vf[0], vf[2]);
                mma16816b(o[ng * 2 + 1], ph[kc], vf[1], vf[3]);
            }
        }
    }

    // ---- epilogue ----
    const float inv0 = 1.0f / l0r, inv1 = 1.0f / l1r;
    const int row0 = b * TSEQ + q0 + wid * 16 + (lane >> 2);
#pragma unroll
    for (int j = 0; j < 16; ++j) {
        const int col = h * 128 + j * 8 + (lane & 3) * 2;
        __half2 h2a = __float22half2_rn(make_float2(o[j][0] * inv0, o[j][1] * inv0));
        __half2 h2b = __float22half2_rn(make_float2(o[j][2] * inv1, o[j][3] * inv1));
        *(__half2*)(outh + (size_t)row0 * DM + col)       = h2a;
        *(__half2*)(outh + (size_t)(row0 + 8) * DM + col) = h2b;
    }
}

// ---------------- host-side helpers ----------------
static void run_conv(const float* src, __half* dst, size_t n) {
    int n4 = (int)(n / 4);
    conv_f16<<<(n4 + 255) / 256, 256>>>(src, dst, n4);
}
template<int BN, int EPI>
static void run_gemm(const __half* a, const __half* b, float* c,
                     __half* ch, __half* ch2, __half* ch3, __half* ch4,
                     int M, int N, int K) {
    constexpr int SMEM = 3 * (128 * 128 + BN * 128);
    cudaFuncSetAttribute(gemm_s<BN, EPI>, cudaFuncAttributeMaxDynamicSharedMemorySize, SMEM);
    gemm_s<BN, EPI><<<dim3(N / BN, M / 128), 256, SMEM>>>(a, b, c, ch, ch2, ch3, ch4, M, N, K);
}

extern "C" void kernel_launch(void* const* d_in, const int* in_sizes, int n_in,
                              void* d_out, int out_size) {
    const float* x      = (const float*)d_in[0];
    const float* w_q    = (const float*)d_in[1];
    const float* w_dkv  = (const float*)d_in[2];
    const float* w_ukv  = (const float*)d_in[3];
    const float* w_o    = (const float*)d_in[4];
    const float* w_qrot = (const float*)d_in[5];
    const float* w_krot = (const float*)d_in[6];
    float* out = (float*)d_out;

    __half *xh,*wcat,*wuh,*woh,*qroth,*kroth,*p_dkv,*p_attn,*pqh,*pkh,*pkrh,*pvh;
    cudaGetSymbolAddress((void**)&xh,    g_x);
    cudaGetSymbolAddress((void**)&wcat,  g_wcat);
    cudaGetSymbolAddress((void**)&wuh,   g_wukv_h);
    cudaGetSymbolAddress((void**)&woh,   g_wo_h);
    cudaGetSymbolAddress((void**)&qroth, g_qroth);
    cudaGetSymbolAddress((void**)&kroth, g_kroth);
    cudaGetSymbolAddress((void**)&p_dkv, g_dkv);
    cudaGetSymbolAddress((void**)&p_attn,g_attn);
    cudaGetSymbolAddress((void**)&pqh,   g_qh);
    cudaGetSymbolAddress((void**)&pkh,   g_kh);
    cudaGetSymbolAddress((void**)&pkrh,  g_krh);
    cudaGetSymbolAddress((void**)&pvh,   g_vh);

    run_conv(x, xh, (size_t)BT * DM);                                        // 0
    {   // 1: all four projection weights -> wcat
        int n4 = 3648 * 2048 / 4;
        conv_cat<<<(n4 + 255) / 256, 256>>>(w_q, w_qrot, w_dkv, w_krot, wcat, n4);
    }
    run_conv(w_ukv, wuh, (size_t)4096 * 512);                                // 2
    // 3: fused projection GEMM (q-pack | qrot | dkv | krot)  <- profiled
    run_gemm<128, 4>(xh, wcat, nullptr, pqh, qroth, p_dkv, kroth, BT, NCAT, DM);
    run_conv(w_o, woh, (size_t)DM * DM);                                     // 4
    // 5: ukv GEMM with K|V split epilogue
    run_gemm<128, 3>(p_dkv, wuh, nullptr, pkh, pvh, nullptr, nullptr, BT, 4096, 512);

    rope_pack_q<<<(32 * TSEQ * 32) / 256, 256>>>(qroth, pqh);                // 6
    rope_pack_k<<<(2 * TSEQ * 32) / 256, 256>>>(kroth, pkrh);                // 7

    cudaFuncSetAttribute(attn_mma, cudaFuncAttributeMaxDynamicSharedMemorySize, ATT_SMEM);
    attn_mma<<<dim3(TSEQ / 256, 32), 512, ATT_SMEM>>>(pqh, pkh, pkrh, pvh, p_attn);  // 8

    run_gemm<128, 0>(p_attn, woh, out, nullptr, nullptr, nullptr, nullptr, BT, DM, DM);  // 9
}

// round 10
// speedup vs baseline: 1.0344x; 1.0344x over previous
#include <cuda_runtime.h>
#include <cuda_fp16.h>
#include <math.h>
#include <cstdint>

#define BT    4096
#define TSEQ  2048
#define DM    2048
#define DQK   192
#define DV    128
#define NCAT  3712
#define ATT_SCALE 0.07216878364870323f   // 1/sqrt(192)
#define NEG_BIG  -1e30f

// ---------------- scratch ----------------
__device__ __half g_x    [BT * DM];
__device__ __half g_wcat [NCAT * DM];
__device__ __half g_wukv_h[4096 * 512];
__device__ __half g_wo_h [DM * DM];
__device__ __half g_qroth[BT * 1024];
__device__ __half g_kroth[BT * 64];
__device__ __half g_dkv  [BT * 512];
__device__ __half g_attn [BT * DM];
__device__ __half g_qh [32 * TSEQ * DQK];
__device__ __half g_kh [32 * TSEQ * 128];
__device__ __half g_krh[ 2 * TSEQ * 64];
__device__ __half g_vh [32 * TSEQ * 128];

// ---------------- PTX helpers ----------------
__device__ __forceinline__ void cp16(uint32_t s, const void* g) {
    asm volatile("cp.async.cg.shared.global [%0], [%1], 16;" :: "r"(s), "l"(g) : "memory");
}
__device__ __forceinline__ uint32_t smem_u32(const void* p) {
    uint32_t a;
    asm("{ .reg .u64 t; cvta.to.shared.u64 t, %1; cvt.u32.u64 %0, t; }" : "=r"(a) : "l"(p));
    return a;
}
__device__ __forceinline__ void ldm4(uint32_t* r, uint32_t addr) {
    asm volatile("ldmatrix.sync.aligned.m8n8.x4.shared.b16 {%0,%1,%2,%3}, [%4];"
        : "=r"(r[0]), "=r"(r[1]), "=r"(r[2]), "=r"(r[3]) : "r"(addr));
}
__device__ __forceinline__ void ldm4t(uint32_t* r, uint32_t addr) {
    asm volatile("ldmatrix.sync.aligned.m8n8.x4.trans.shared.b16 {%0,%1,%2,%3}, [%4];"
        : "=r"(r[0]), "=r"(r[1]), "=r"(r[2]), "=r"(r[3]) : "r"(addr));
}
__device__ __forceinline__ void mma16816(float* c, const uint32_t* a, const uint32_t* b) {
    asm volatile(
        "mma.sync.aligned.m16n8k16.row.col.f32.f16.f16.f32 "
        "{%0,%1,%2,%3}, {%4,%5,%6,%7}, {%8,%9}, {%0,%1,%2,%3};"
        : "+f"(c[0]), "+f"(c[1]), "+f"(c[2]), "+f"(c[3])
        : "r"(a[0]), "r"(a[1]), "r"(a[2]), "r"(a[3]), "r"(b[0]), "r"(b[1]));
}
__device__ __forceinline__ void mma16816b(float* c, const uint32_t* a, uint32_t b0, uint32_t b1) {
    asm volatile(
        "mma.sync.aligned.m16n8k16.row.col.f32.f16.f16.f32 "
        "{%0,%1,%2,%3}, {%4,%5,%6,%7}, {%8,%9}, {%0,%1,%2,%3};"
        : "+f"(c[0]), "+f"(c[1]), "+f"(c[2]), "+f"(c[3])
        : "r"(a[0]), "r"(a[1]), "r"(a[2]), "r"(a[3]), "r"(b0), "r"(b1));
}

// ---------------- converts ----------------
__global__ void conv_f16(const float* __restrict__ in, __half* __restrict__ out, int n4) {
    int i = blockIdx.x * blockDim.x + threadIdx.x;
    if (i >= n4) return;
    float4 v = ((const float4*)in)[i];
    ((__half2*)out)[i*2]   = __halves2half2(__float2half_rn(v.x), __float2half_rn(v.y));
    ((__half2*)out)[i*2+1] = __halves2half2(__float2half_rn(v.z), __float2half_rn(v.w));
}
__global__ void conv_cat(const float* __restrict__ wq, const float* __restrict__ wqr,
                         const float* __restrict__ wdkv, const float* __restrict__ wkr,
                         __half* __restrict__ out, int n4) {
    int i = blockIdx.x * blockDim.x + threadIdx.x;
    if (i >= n4) return;
    const size_t e = (size_t)i * 4;
    const int row = (int)(e >> 11);
    const float* src;
    size_t local;
    float sc;
    if (row < 2048)      { src = wq;   local = e;                       sc = ATT_SCALE; }
    else if (row < 3072) { src = wqr;  local = e - (size_t)2048 * 2048; sc = ATT_SCALE; }
    else if (row < 3584) { src = wdkv; local = e - (size_t)3072 * 2048; sc = 1.f; }
    else                 { src = wkr;  local = e - (size_t)3584 * 2048; sc = 1.f; }
    float4 v = *(const float4*)(src + local);
    ((__half2*)out)[i*2]   = __halves2half2(__float2half_rn(v.x * sc), __float2half_rn(v.y * sc));
    ((__half2*)out)[i*2+1] = __halves2half2(__float2half_rn(v.z * sc), __float2half_rn(v.w * sc));
}

// ---------------- single-pass fp16 NT GEMM, 3-stage / 1-sync pipeline ----------------
// EPI: 0 fp32 C; 3 ukv split; 4 fused projection router
template<int BN, int EPI>
__global__ __launch_bounds__(256, 2)
void gemm_s(const __half* __restrict__ A, const __half* __restrict__ B,
            float* __restrict__ C, __half* __restrict__ CH, __half* __restrict__ CH2,
            __half* __restrict__ CH3, __half* __restrict__ CH4,
            int M, int N, int K)
{
    constexpr int ATILE = 128 * 128;
    constexpr int BTILE = BN * 128;
    constexpr int STG   = ATILE + BTILE;
    constexpr int WN = 4;
    constexpr int MT = 4;
    constexpr int NT = 4;

    extern __shared__ __align__(128) char smem[];
    const uint32_t d0 = smem_u32(smem);

    const int tid = threadIdx.x;
    const int wid = tid >> 5, lane = tid & 31;
    const int wn = wid % WN, wm = wid / WN;
    const int m0 = blockIdx.y * 128;
    const int n0 = blockIdx.x * BN;
    const int l7 = lane & 7;

    float acc[MT][NT][4];
#pragma unroll
    for (int i = 0; i < MT; ++i)
#pragma unroll
        for (int j = 0; j < NT; ++j)
#pragma unroll
            for (int q = 0; q < 4; ++q) acc[i][j][q] = 0.f;

    uint32_t arow[MT], brow[NT / 2];
    const int a_r = lane & 15;
    const int a_kh = lane >> 4;
    const int b_n = ((lane >> 4) << 3) + (lane & 7);
    const int b_kh = (lane >> 3) & 1;
#pragma unroll
    for (int mt = 0; mt < MT; ++mt) arow[mt] = (uint32_t)((wm * 64 + mt * 16 + a_r) * 128);
#pragma unroll
    for (int np = 0; np < NT / 2; ++np) brow[np] = (uint32_t)((wn * 32 + np * 16 + b_n) * 128);

    const int T = K >> 6;
    auto load_tile = [&](int t) {
        if (t < T) {
            const uint32_t d = d0 + (uint32_t)(t % 3) * STG;
            const int k0 = t * 64;
#pragma unroll
            for (int j = 0; j < 4; ++j) {
                const int c = tid + j * 256;
                const int row = c >> 3, ch = c & 7;
                const uint32_t sw = (uint32_t)(row * 128 + ((ch ^ (row & 7)) << 4));
                cp16(d + sw, A + (size_t)(m0 + row) * K + k0 + ch * 8);
            }
#pragma unroll
            for (int j = 0; j < BN / 32; ++j) {
                const int c = tid + j * 256;
                const int row = c >> 3, ch = c & 7;
                const uint32_t sw = (uint32_t)(row * 128 + ((ch ^ (row & 7)) << 4));
                cp16(d + ATILE + sw, B + (size_t)(n0 + row) * K + k0 + ch * 8);
            }
        }
        asm volatile("cp.async.commit_group;" ::: "memory");
    };

    load_tile(0);
    load_tile(1);

    for (int t = 0; t < T; ++t) {
        asm volatile("cp.async.wait_group 1;" ::: "memory");
        __syncthreads();
        load_tile(t + 2);

        const uint32_t AS = d0 + (uint32_t)(t % 3) * STG;
        const uint32_t BS = AS + ATILE;

#pragma unroll
        for (int kk = 0; kk < 4; ++kk) {
            const uint32_t aoff = (uint32_t)(((kk * 2 + a_kh) ^ l7) << 4);
            const uint32_t boff = (uint32_t)(((kk * 2 + b_kh) ^ l7) << 4);
            uint32_t af[MT][4], bf[NT / 2][4];
#pragma unroll
            for (int mt = 0; mt < MT; ++mt)
                ldm4(af[mt], AS + arow[mt] + aoff);
#pragma unroll
            for (int np = 0; np < NT / 2; ++np)
                ldm4(bf[np], BS + brow[np] + boff);
#pragma unroll
            for (int mt = 0; mt < MT; ++mt)
#pragma unroll
                for (int nt = 0; nt < NT; ++nt)
                    mma16816(acc[mt][nt], af[mt], &bf[nt >> 1][(nt & 1) * 2]);
        }
    }

    const int cr = lane >> 2;
    const int cc = (lane & 3) * 2;
#pragma unroll
    for (int mt = 0; mt < MT; ++mt) {
        const int r0 = m0 + wm * 64 + mt * 16 + cr;
#pragma unroll
        for (int nt = 0; nt < NT; ++nt) {
            const int col = n0 + wn * 32 + nt * 8 + cc;
            if constexpr (EPI == 0) {
                *(float2*)(C + (size_t)r0 * N + col)       = make_float2(acc[mt][nt][0], acc[mt][nt][1]);
                *(float2*)(C + (size_t)(r0 + 8) * N + col) = make_float2(acc[mt][nt][2], acc[mt][nt][3]);
            } else {
#pragma unroll
                for (int hf = 0; hf < 2; ++hf) {
                    __half2 h2 = __float22half2_rn(
                        make_float2(acc[mt][nt][hf*2], acc[mt][nt][hf*2+1]));
                    const int r = r0 + hf * 8;
                    const int b = r >> 11, tt = r & 2047;
                    if constexpr (EPI == 3) {
                        const int h = col >> 8, c = col & 255;
                        const size_t base = ((size_t)((b * 16 + h) * 2048 + tt)) * 128;
                        if (c < 128) *(__half2*)(CH  + base + c)         = h2;
                        else         *(__half2*)(CH2 + base + (c - 128)) = h2;
                    } else {   // EPI == 4
                        if (col < 2048) {
                            const int h = col >> 7, c = col & 127;
                            *(__half2*)(CH + ((size_t)((b * 16 + h) * 2048 + tt)) * 192 + c) = h2;
                        } else if (col < 3072) {
                            *(__half2*)(CH2 + (size_t)r * 1024 + (col - 2048)) = h2;
                        } else if (col < 3584) {
                            *(__half2*)(CH3 + (size_t)r * 512 + (col - 3072)) = h2;
                        } else if (col < 3648) {
                            *(__half2*)(CH4 + (size_t)r * 64 + (col - 3584)) = h2;
                        }
                    }
                }
            }
        }
    }
}

// ---------------- fused rope + pack ----------------
__device__ __forceinline__ void rope_pair(float x1, float x2, int i, int t,
                                          float& o1, float& o2) {
    const float invf = (float)exp2(-(double)i * (13.287712379549449 / 32.0));
    const float angf = (float)t * invf;
    double sd, cd;
    sincos((double)angf, &sd, &cd);
    const float s = (float)sd, c = (float)cd;
    o1 = x1 * c - x2 * s;
    o2 = x2 * c + x1 * s;
}
__global__ void rope_pack_q(const __half* __restrict__ qr, __half* __restrict__ oh) {
    int idx = blockIdx.x * blockDim.x + threadIdx.x;
    int i = idx & 31;
    int rest = idx >> 5;
    int bh = rest >> 11, t = rest & 2047;
    int b = bh >> 4, h = bh & 15;
    const __half* base = qr + ((size_t)(b * TSEQ + t)) * 1024 + h * 64;
    float o1, o2;
    rope_pair(__half2float(base[i]), __half2float(base[i + 32]), i, t, o1, o2);
    __half* dst = oh + ((size_t)bh * TSEQ + t) * DQK + 128;
    dst[i]      = __float2half_rn(o1);
    dst[i + 32] = __float2half_rn(o2);
}
__global__ void rope_pack_k(const __half* __restrict__ kr, __half* __restrict__ oh) {
    int idx = blockIdx.x * blockDim.x + threadIdx.x;
    int i = idx & 31;
    int rest = idx >> 5;
    int t = rest & 2047;
    const __half* base = kr + (size_t)rest * 64;
    float o1, o2;
    rope_pair(__half2float(base[i]), __half2float(base[i + 32]), i, t, o1, o2);
    __half* dst = oh + (size_t)rest * 64;
    dst[i]      = __float2half_rn(o1);
    dst[i + 32] = __float2half_rn(o2);
}

// ---------------- tensor-core flash attention: BQ=128, BK=32, occ 2 ----------------
#define QPL  49152           // 128 rows x 384B
#define KPL  12288           // 32 x 384B
#define VPL  8192            // 32 x 256B
#define KVSTG (KPL + VPL)    // 20480
#define ATT_SMEM (QPL + 3*KVSTG)   // 110592 -> 2 CTAs/SM

__global__ __launch_bounds__(256, 2) void attn_mma(
    const __half* __restrict__ qh, const __half* __restrict__ kh,
    const __half* __restrict__ krh, const __half* __restrict__ vh,
    __half* __restrict__ outh)
{
    extern __shared__ __align__(128) char smem[];
    const uint32_t S0 = smem_u32(smem);
    const int tid = threadIdx.x, wid = tid >> 5, lane = tid & 31;
    const int qt = gridDim.x - 1 - blockIdx.x;      // heavy tiles first
    const int bh = blockIdx.y;
    const int b = bh >> 4, h = bh & 15;
    const int q0 = qt * 128;
    const int nk = 4 * (qt + 1);                    // 32-wide k-tiles

    const size_t qbase = (size_t)bh * TSEQ * DQK;
    const size_t kbase = (size_t)bh * TSEQ * 128;
    const size_t rbase = (size_t)b * TSEQ * 64;

    {   // Q (group 0)
        for (int i = tid; i < 128 * 24; i += 256) {
            int row = i / 24, c = i % 24;
            uint32_t sw = (uint32_t)(row * 384 + ((c ^ (row & 7)) << 4));
            cp16(S0 + sw, qh + qbase + (size_t)(q0 + row) * DQK + c * 8);
        }
        asm volatile("cp.async.commit_group;" ::: "memory");
    }
    auto loadKV = [&](int it) {
        if (it < nk) {
            uint32_t d = S0 + QPL + (uint32_t)(it % 3) * KVSTG;
            int k0 = it * 32;
#pragma unroll
            for (int j = 0; j < 3; ++j) {            // K: 32 rows x 24 chunks
                int i = tid + j * 256;
                int row = i / 24, c = i % 24;
                uint32_t sw = (uint32_t)(row * 384 + ((c ^ (row & 7)) << 4));
                const __half* src = (c < 16)
                    ? kh  + kbase + (size_t)(k0 + row) * 128 + c * 8
                    : krh + rbase + (size_t)(k0 + row) * 64 + (c - 16) * 8;
                cp16(d + sw, src);
            }
            uint32_t dv = d + KPL;
#pragma unroll
            for (int j = 0; j < 2; ++j) {            // V: 32 rows x 16 chunks
                int i = tid + j * 256;
                int row = i >> 4, c = i & 15;
                uint32_t sw = (uint32_t)(row * 256 + (((c & 8) | ((c & 7) ^ (row & 7))) << 4));
                cp16(dv + sw, vh + kbase + (size_t)(k0 + row) * 128 + c * 8);
            }
        }
        asm volatile("cp.async.commit_group;" ::: "memory");
    };

    loadKV(0);
    loadKV(1);

    const int a_r = lane & 15, a_kh = lane >> 4;
    const int b_n = ((lane >> 4) << 3) + (lane & 7), b_kh = (lane >> 3) & 1;
    const int qrow = wid * 16 + a_r;
    const uint32_t qoff_base = S0 + qrow * 384;
    const int v_tl = lane >> 3, v_r = lane & 7;

    float o[16][4];
#pragma unroll
    for (int j = 0; j < 16; ++j)
#pragma unroll
        for (int q = 0; q < 4; ++q) o[j][q] = 0.f;
    float m0r = NEG_BIG, m1r = NEG_BIG, l0r = 0.f, l1r = 0.f;

    for (int it = 0; it < nk; ++it) {
        asm volatile("cp.async.wait_group 1;" ::: "memory");
        __syncthreads();
        loadKV(it + 2);   // stage (it+2)%3 == (it-1)%3, already consumed

        const uint32_t Kb = S0 + QPL + (uint32_t)(it % 3) * KVSTG;
        const uint32_t Vb = Kb + KPL;

        // ---- S = Q K^T (128x32) ----
        float s[4][4];
#pragma unroll
        for (int j = 0; j < 4; ++j)
#pragma unroll
            for (int q = 0; q < 4; ++q) s[j][q] = 0.f;

#pragma unroll 4
        for (int kc = 0; kc < 12; ++kc) {
            uint32_t qa = qoff_base + ((((kc * 2 + a_kh)) ^ (qrow & 7)) << 4);
            uint32_t qf[4];
            ldm4(qf, qa);
#pragma unroll
            for (int np = 0; np < 2; ++np) {
                int krow = np * 16 + b_n;
                uint32_t ka = Kb + krow * 384 + (((kc * 2 + b_kh) ^ (krow & 7)) << 4);
                uint32_t kf[4];
                ldm4(kf, ka);
#pragma unroll
                for (int t2 = 0; t2 < 2; ++t2)
                    mma16816(s[np * 2 + t2], qf, &kf[t2 * 2]);
            }
        }

        // ---- mask (last four k-tiles: diagonal block) ----
        const int k0 = it * 32;
        const int r0 = q0 + wid * 16 + (lane >> 2);
        if (it >= nk - 4) {
#pragma unroll
            for (int nt = 0; nt < 4; ++nt) {
                int kcol = k0 + nt * 8 + (lane & 3) * 2;
                if (kcol     > r0)     s[nt][0] = NEG_BIG;
                if (kcol + 1 > r0)     s[nt][1] = NEG_BIG;
                if (kcol     > r0 + 8) s[nt][2] = NEG_BIG;
                if (kcol + 1 > r0 + 8) s[nt][3] = NEG_BIG;
            }
        }

        // ---- online softmax ----
        float mx0 = NEG_BIG, mx1 = NEG_BIG;
#pragma unroll
        for (int nt = 0; nt < 4; ++nt) {
            mx0 = fmaxf(mx0, fmaxf(s[nt][0], s[nt][1]));
            mx1 = fmaxf(mx1, fmaxf(s[nt][2], s[nt][3]));
        }
        mx0 = fmaxf(mx0, __shfl_xor_sync(0xffffffffu, mx0, 1));
        mx0 = fmaxf(mx0, __shfl_xor_sync(0xffffffffu, mx0, 2));
        mx1 = fmaxf(mx1, __shfl_xor_sync(0xffffffffu, mx1, 1));
        mx1 = fmaxf(mx1, __shfl_xor_sync(0xffffffffu, mx1, 2));
        const float mn0 = fmaxf(m0r, mx0), mn1 = fmaxf(m1r, mx1);
        const float al0 = __expf(m0r - mn0), al1 = __expf(m1r - mn1);
        m0r = mn0; m1r = mn1;

        float sum0 = 0.f, sum1 = 0.f;
        uint32_t ph[2][4];
#pragma unroll
        for (int nt = 0; nt < 4; ++nt) {
            float p0 = __expf(s[nt][0] - mn0);
            float p1 = __expf(s[nt][1] - mn0);
            float p2 = __expf(s[nt][2] - mn1);
            float p3 = __expf(s[nt][3] - mn1);
            sum0 += p0 + p1;
            sum1 += p2 + p3;
            __half2 h01 = __float22half2_rn(make_float2(p0, p1));
            __half2 h23 = __float22half2_rn(make_float2(p2, p3));
            const int kc2 = nt >> 1, w2 = (nt & 1) * 2;
            ph[kc2][w2]     = *(uint32_t*)&h01;
            ph[kc2][w2 + 1] = *(uint32_t*)&h23;
        }
        sum0 += __shfl_xor_sync(0xffffffffu, sum0, 1);
        sum0 += __shfl_xor_sync(0xffffffffu, sum0, 2);
        sum1 += __shfl_xor_sync(0xffffffffu, sum1, 1);
        sum1 += __shfl_xor_sync(0xffffffffu, sum1, 2);
        l0r = l0r * al0 + sum0;
        l1r = l1r * al1 + sum1;

#pragma unroll
        for (int j = 0; j < 16; ++j) {
            o[j][0] *= al0; o[j][1] *= al0;
            o[j][2] *= al1; o[j][3] *= al1;
        }

        // ---- O += P V  (V [t][dv] via ldmatrix.trans) ----
#pragma unroll
        for (int kc = 0; kc < 2; ++kc) {
#pragma unroll
            for (int ng = 0; ng < 8; ++ng) {
                const int trow = kc * 16 + ((v_tl >> 1) << 3) + v_r;
                const int c = ng * 2 + (v_tl & 1);
                uint32_t va = Vb + trow * 256 +
                    ((uint32_t)((c & 8) | ((c & 7) ^ (trow & 7))) << 4);
                uint32_t vf[4];
                ldm4t(vf, va);
                mma16816b(o[ng * 2],     ph[kc], vf[0], vf[2]);
                mma16816b(o[ng * 2 + 1], ph[kc], vf[1], vf[3]);
            }
        }
    }

    // ---- epilogue ----
    const float inv0 = 1.0f / l0r, inv1 = 1.0f / l1r;
    const int row0 = b * TSEQ + q0 + wid * 16 + (lane >> 2);
#pragma unroll
    for (int j = 0; j < 16; ++j) {
        const int col = h * 128 + j * 8 + (lane & 3) * 2;
        __half2 h2a = __float22half2_rn(make_float2(o[j][0] * inv0, o[j][1] * inv0));
        __half2 h2b = __float22half2_rn(make_float2(o[j][2] * inv1, o[j][3] * inv1));
        *(__half2*)(outh + (size_t)row0 * DM + col)       = h2a;
        *(__half2*)(outh + (size_t)(row0 + 8) * DM + col) = h2b;
    }
}

// ---------------- host-side helpers ----------------
static void run_conv(const float* src, __half* dst, size_t n) {
    int n4 = (int)(n / 4);
    conv_f16<<<(n4 + 255) / 256, 256>>>(src, dst, n4);
}
template<int BN, int EPI>
static void run_gemm(const __half* a, const __half* b, float* c,
                     __half* ch, __half* ch2, __half* ch3, __half* ch4,
                     int M, int N, int K) {
    constexpr int SMEM = 3 * (128 * 128 + BN * 128);
    cudaFuncSetAttribute(gemm_s<BN, EPI>, cudaFuncAttributeMaxDynamicSharedMemorySize, SMEM);
    gemm_s<BN, EPI><<<dim3(N / BN, M / 128), 256, SMEM>>>(a, b, c, ch, ch2, ch3, ch4, M, N, K);
}

extern "C" void kernel_launch(void* const* d_in, const int* in_sizes, int n_in,
                              void* d_out, int out_size) {
    const float* x      = (const float*)d_in[0];
    const float* w_q    = (const float*)d_in[1];
    const float* w_dkv  = (const float*)d_in[2];
    const float* w_ukv  = (const float*)d_in[3];
    const float* w_o    = (const float*)d_in[4];
    const float* w_qrot = (const float*)d_in[5];
    const float* w_krot = (const float*)d_in[6];
    float* out = (float*)d_out;

    __half *xh,*wcat,*wuh,*woh,*qroth,*kroth,*p_dkv,*p_attn,*pqh,*pkh,*pkrh,*pvh;
    cudaGetSymbolAddress((void**)&xh,    g_x);
    cudaGetSymbolAddress((void**)&wcat,  g_wcat);
    cudaGetSymbolAddress((void**)&wuh,   g_wukv_h);
    cudaGetSymbolAddress((void**)&woh,   g_wo_h);
    cudaGetSymbolAddress((void**)&qroth, g_qroth);
    cudaGetSymbolAddress((void**)&kroth, g_kroth);
    cudaGetSymbolAddress((void**)&p_dkv, g_dkv);
    cudaGetSymbolAddress((void**)&p_attn,g_attn);
    cudaGetSymbolAddress((void**)&pqh,   g_qh);
    cudaGetSymbolAddress((void**)&pkh,   g_kh);
    cudaGetSymbolAddress((void**)&pkrh,  g_krh);
    cudaGetSymbolAddress((void**)&pvh,   g_vh);

    run_conv(x, xh, (size_t)BT * DM);                                        // 0
    {   // 1
        int n4 = 3648 * 2048 / 4;
        conv_cat<<<(n4 + 255) / 256, 256>>>(w_q, w_qrot, w_dkv, w_krot, wcat, n4);
    }
    run_conv(w_ukv, wuh, (size_t)4096 * 512);                                // 2
    run_gemm<128, 4>(xh, wcat, nullptr, pqh, qroth, p_dkv, kroth, BT, NCAT, DM);  // 3 <- profiled
    run_conv(w_o, woh, (size_t)DM * DM);                                     // 4
    run_gemm<128, 3>(p_dkv, wuh, nullptr, pkh, pvh, nullptr, nullptr, BT, 4096, 512);  // 5

    rope_pack_q<<<(32 * TSEQ * 32) / 256, 256>>>(qroth, pqh);                // 6
    rope_pack_k<<<(2 * TSEQ * 32) / 256, 256>>>(kroth, pkrh);                // 7

    cudaFuncSetAttribute(attn_mma, cudaFuncAttributeMaxDynamicSharedMemorySize, ATT_SMEM);
    attn_mma<<<dim3(TSEQ / 128, 32), 256, ATT_SMEM>>>(pqh, pkh, pkrh, pvh, p_attn);  // 8

    run_gemm<128, 0>(p_attn, woh, out, nullptr, nullptr, nullptr, nullptr, BT, DM, DM);  // 9
}